// round 10
// baseline (speedup 1.0000x reference)
#include <cuda_runtime.h>
#include <cuda_bf16.h>
#include <math.h>

// ---------------------------------------------------------------------------
// AliasFreeConv: modulated 3x3 conv (demod) + 2x up (12-tap) + lrelu + 2x down
// Conv: bf16 split-precision (3-pass) implicit GEMM on mma.sync + ldmatrix.
// R10: chunk-major K schedule + sliced X staging (removes early-wait stalls).
// Launch order: pre1, pre2, prep_x, conv(#4 - profiled), filter.
// ---------------------------------------------------------------------------

#define BATCH 8
#define CIN   512
#define COUT  512
#define HW    64
#define HC    62
#define HU    128
#define NTAPS 12
#define XP    68              // padded spatial for channels-last input

#define LIN_SCALE 0.044194173824159216f   // 1/sqrt(512)
#define WSCALE    0.014731391274719742f   // 1/sqrt(512*9)
#define WSCALE2   2.170138888888889e-4f   // 1/4608
#define EPSV      1e-8f
#define NEG_SLOPE 0.2f
#define LRELU_SC  1.4142135623730951f

#define XT_ELEMS (BATCH*XP*XP*512)        // 18,939,904
#define WT_ELEMS (9*512*512)              // 2,359,296

// ------------------------- scratch (device globals) ------------------------
__device__ float g_s  [BATCH*CIN];
__device__ float g_g  [BATCH*COUT];
__device__ float g_wsq[COUT*CIN];
__device__ float g_A  [BATCH*COUT*HC*HC];               // conv output (63 MB)
__device__ __align__(16) __nv_bfloat16 g_xhi[XT_ELEMS]; // x*wscale*s, hi part
__device__ __align__(16) __nv_bfloat16 g_xlo[XT_ELEMS]; // lo part
__device__ __align__(16) __nv_bfloat16 g_whi[WT_ELEMS]; // [tap][co][ci]
__device__ __align__(16) __nv_bfloat16 g_wlo[WT_ELEMS];

// ------------------------- PTX helpers -------------------------------------
__device__ __forceinline__ unsigned smem_u32(const void* p) {
    unsigned a;
    asm("{ .reg .u64 t; cvta.to.shared.u64 t, %1; cvt.u32.u64 %0, t; }"
        : "=r"(a) : "l"(p));
    return a;
}
__device__ __forceinline__ void cp16(unsigned dst, const void* src) {
    asm volatile("cp.async.cg.shared.global [%0], [%1], 16;"
                 :: "r"(dst), "l"(src) : "memory");
}
__device__ __forceinline__ void cp_commit() {
    asm volatile("cp.async.commit_group;" ::: "memory");
}
__device__ __forceinline__ void cp_wait0() {
    asm volatile("cp.async.wait_group 0;" ::: "memory");
}
__device__ __forceinline__ void cp_wait1() {
    asm volatile("cp.async.wait_group 1;" ::: "memory");
}
#define MMA16816(d, a0, a1, a2, a3, b0, b1) \
    asm volatile("mma.sync.aligned.m16n8k16.row.col.f32.bf16.bf16.f32 " \
        "{%0,%1,%2,%3}, {%4,%5,%6,%7}, {%8,%9}, {%0,%1,%2,%3};" \
        : "+f"((d)[0]), "+f"((d)[1]), "+f"((d)[2]), "+f"((d)[3]) \
        : "r"(a0), "r"(a1), "r"(a2), "r"(a3), "r"(b0), "r"(b1))
#define LDSM4(r0, r1, r2, r3, addr) \
    asm volatile("ldmatrix.sync.aligned.m8n8.x4.shared.b16 {%0,%1,%2,%3}, [%4];" \
        : "=r"(r0), "=r"(r1), "=r"(r2), "=r"(r3) : "r"(addr))

// ------------------------- L1: style + wsq + zero x_t ----------------------
__global__ __launch_bounds__(256)
void k_pre1(const float* __restrict__ style, const float* __restrict__ mod_w,
            const float* __restrict__ mod_b, const float* __restrict__ cw) {
    int bid = blockIdx.x;
    int tid = threadIdx.x;
    if (bid < 512) {
        int w    = bid * 8 + (tid >> 5);
        int lane = tid & 31;
        int b = w >> 9, c = w & 511;
        const float* sp = style + b * 512;
        const float* mp = mod_w + c * 512;
        float sum = 0.f;
        #pragma unroll 4
        for (int d = lane; d < 512; d += 32) sum += sp[d] * mp[d];
        #pragma unroll
        for (int off = 16; off; off >>= 1)
            sum += __shfl_xor_sync(0xffffffffu, sum, off);
        if (lane == 0) g_s[w] = sum * LIN_SCALE + mod_b[c];
    } else if (bid < 1536) {
        int i = (bid - 512) * 256 + tid;
        if (i < COUT * CIN) {
            float s = 0.f;
            #pragma unroll
            for (int k = 0; k < 9; k++) { float v = cw[i * 9 + k]; s += v * v; }
            g_wsq[i] = s;
        }
    } else {
        uint4 z = make_uint4(0u, 0u, 0u, 0u);
        uint4* a = reinterpret_cast<uint4*>(g_xhi);
        uint4* bb = reinterpret_cast<uint4*>(g_xlo);
        int n = XT_ELEMS / 8;
        for (int i = (bid - 1536) * 256 + tid; i < n; i += 4096 * 256) {
            a[i] = z; bb[i] = z;
        }
    }
}

// ------------------------- L2: demod + prep_w ------------------------------
__global__ __launch_bounds__(256)
void k_pre2(const float* __restrict__ cw) {
    int bid = blockIdx.x;
    int tid = threadIdx.x;
    if (bid < 512) {
        int w    = bid * 8 + (tid >> 5);
        int lane = tid & 31;
        int b = w >> 9, co = w & 511;
        const float* sp = g_s   + b  * 512;
        const float* wq = g_wsq + co * 512;
        float sum = 0.f;
        #pragma unroll 4
        for (int d = lane; d < 512; d += 32) {
            float sv = sp[d]; sum += sv * sv * wq[d];
        }
        #pragma unroll
        for (int off = 16; off; off >>= 1)
            sum += __shfl_xor_sync(0xffffffffu, sum, off);
        if (lane == 0) g_g[w] = 1.0f / ((1.0f + EPSV) * sqrtf(WSCALE2 * sum + EPSV));
    } else {
        int i = (bid - 512) * 256 + tid;
        if (i < WT_ELEMS) {
            int ci  = i & 511;
            int co  = (i >> 9) & 511;
            int tap = i >> 18;
            float v = cw[(co * 512 + ci) * 9 + tap];
            __nv_bfloat16 hi = __float2bfloat16(v);
            __nv_bfloat16 lo = __float2bfloat16(v - __bfloat162float(hi));
            g_whi[i] = hi;
            g_wlo[i] = lo;
        }
    }
}

// ------------------------- L3: x -> channels-last bf16 hi/lo ---------------
__global__ __launch_bounds__(256)
void k_prep_x(const float* __restrict__ x) {
    __shared__ float t[32][33];
    int bid  = blockIdx.x;                 // b(8) * y(64) * ciT(16) * xT(2)
    int xt   = bid & 1;
    int ci_t = (bid >> 1) & 15;
    int y    = (bid >> 5) & 63;
    int b    = bid >> 11;
    int tx = threadIdx.x & 31, ty = threadIdx.x >> 5;   // (32, 8)

    #pragma unroll
    for (int j = 0; j < 4; j++) {
        int ci = ci_t * 32 + ty + 8 * j;
        int xx = xt * 32 + tx;
        float v = x[((((b << 9) + ci) << 6) + y) * 64 + xx];
        t[ty + 8 * j][tx] = v * (WSCALE * g_s[(b << 9) + ci]);
    }
    __syncthreads();
    #pragma unroll
    for (int j = 0; j < 4; j++) {
        int xx = xt * 32 + ty + 8 * j;
        int ci = ci_t * 32 + tx;
        float v = t[tx][ty + 8 * j];
        __nv_bfloat16 hi = __float2bfloat16(v);
        __nv_bfloat16 lo = __float2bfloat16(v - __bfloat162float(hi));
        long o = ((long)(b * XP + y) * XP + xx) * 512 + ci;
        g_xhi[o] = hi;
        g_xlo[o] = lo;
    }
}

// ------------------------- L4: mma.sync conv (ldmatrix) --------------------
// CTA tile: M=128 co x N=128 pixels (8y x 16x). 8 warps = 2(m) x 4(n),
// warp tile 64x32, mma m16n8k16. 216 K=64 iterations:
//   iters [0,144):  chunk-major hi phase — X window k = i/18 uses xhi(chunk k),
//                   taps: whi 0..8 then wlo 0..8 (t = i%18).
//   iters [144,216): lo phase — 9-iter windows, X = xlo(chunk), whi taps.
// X tile for the NEXT window is staged in 8 slices (180 cp16 each), one per
// iteration, committed with that iteration's W group; wait_group 1 then never
// demands data with <1 iteration of slack. W triple-buffered, distance 2.
// smem: Xs0 @0, Xs1 @25920, Ws @51840 + buf*18432 (3 bufs) -> 107136 B.
#define XS_STRIDE 144
#define OFF_WS    51840
#define WS_BYTES  18432
#define XS_BYTES  25920
#define SMEM_CONV2 107136

__global__ __launch_bounds__(256, 2)
void k_conv_mma(const float* __restrict__ act_b) {
    extern __shared__ __align__(16) char smc[];
    unsigned sbase = smem_u32(smc);

    int tid  = threadIdx.x;
    int wid  = tid >> 5, lane = tid & 31;
    int g    = lane >> 2, t4 = lane & 3;
    int wm   = wid >> 2;                      // 0..1 -> co offset wm*64
    int wn   = wid & 3;                       // 0..3 -> pixel offset wn*32

    int bidx = blockIdx.x;                    // 1024 = b(8)*coT(4)*yT(8)*xT(4)
    int xT   = bidx & 3;
    int yT   = (bidx >> 2) & 7;
    int coT  = (bidx >> 5) & 3;
    int b    = bidx >> 7;
    int co0  = coT << 7;
    int y0   = yT << 3;
    int x0   = xT << 4;

    const __nv_bfloat16* xhiB = g_xhi + (long)b * XP * XP * 512;
    const __nv_bfloat16* xloB = g_xlo + (long)b * XP * XP * 512;

    float acc[4][4][4];
    #pragma unroll
    for (int mi = 0; mi < 4; mi++)
        #pragma unroll
        for (int ni = 0; ni < 4; ni++)
            #pragma unroll
            for (int q = 0; q < 4; q++) acc[mi][ni][q] = 0.f;

    // ---- W source for iteration it ----
    auto stageW = [&](int it, int buf) {
        const __nv_bfloat16* wbase;
        int tap, ci0;
        if (it < 144) {
            int c = it / 18, t = it - c * 18;
            wbase = (t < 9) ? g_whi : g_wlo;
            tap   = (t < 9) ? t : t - 9;
            ci0   = c << 6;
        } else {
            int j = it - 144;
            int c = j / 9;
            wbase = g_whi;
            tap   = j - c * 9;
            ci0   = c << 6;
        }
        const __nv_bfloat16* wp =
            wbase + ((long)tap << 18) + (long)co0 * 512 + ci0;
        unsigned dst = sbase + OFF_WS + buf * WS_BYTES;
        #pragma unroll
        for (int k = 0; k < 4; k++) {                 // 1024 x 16B
            int c = tid + (k << 8);
            int row = c >> 3, cc = c & 7;
            cp16(dst + row * XS_STRIDE + (cc << 4), wp + row * 512 + (cc << 3));
        }
    };
    // ---- X window k (0..15): k<8 -> xhi(chunk k), else xlo(chunk k-8) ----
    auto stageXslice = [&](int k, int s) {            // slice s in 0..7
        int chunk = k & 7;
        const __nv_bfloat16* xp = ((k < 8) ? xhiB : xloB) + (chunk << 6);
        unsigned dst = sbase + (unsigned)(k & 1) * XS_BYTES;
        int c = s * 180 + tid;
        if (tid < 180) {
            int row = c >> 3, cc = c & 7;
            int gy = y0 + row / 18, gx = x0 + row % 18;
            cp16(dst + row * XS_STRIDE + (cc << 4),
                 xp + (long)(gy * XP + gx) * 512 + (cc << 3));
        }
    };
    auto stageXfull = [&](int k) {
        int chunk = k & 7;
        const __nv_bfloat16* xp = ((k < 8) ? xhiB : xloB) + (chunk << 6);
        unsigned dst = sbase + (unsigned)(k & 1) * XS_BYTES;
        for (int c = tid; c < 180 * 8; c += 256) {
            int row = c >> 3, cc = c & 7;
            int gy = y0 + row / 18, gx = x0 + row % 18;
            cp16(dst + row * XS_STRIDE + (cc << 4),
                 xp + (long)(gy * XP + gx) * 512 + (cc << 3));
        }
    };

    // prologue: X window 0 + W(0), W(1) resident before iter 0
    stageXfull(0);
    stageW(0, 0);
    cp_commit();
    stageW(1, 1);
    cp_commit();
    cp_wait0();
    __syncthreads();

    // per-lane ldmatrix base offsets
    unsigned aBaseRow = (unsigned)((wm * 64 + (lane & 15)) * XS_STRIDE)
                        + (((unsigned)lane >> 4) << 4);
    int pxc = (((lane >> 4) & 1) << 3) + (lane & 7);
    unsigned bCol16 = (((unsigned)lane >> 3) & 1) << 4;

    #pragma unroll 1
    for (int i = 0; i < 216; i++) {
        // window bookkeeping
        int kwin, pos, tap;
        if (i < 144) {
            kwin = i / 18; pos = i - kwin * 18;
            tap = (pos < 9) ? pos : pos - 9;
        } else {
            int j = i - 144;
            int c = j / 9;
            kwin = 8 + c; pos = j - c * 9;
            tap = pos;
        }

        if (i + 2 < 216) stageW(i + 2, (i + 2) % 3);
        if (pos < 8 && kwin < 15) stageXslice(kwin + 1, pos);
        cp_commit();

        // compute iteration i
        {
            int ky = tap / 3, kx = tap - 3 * (tap / 3);
            unsigned aB = sbase + OFF_WS + (unsigned)(i % 3) * WS_BYTES + aBaseRow;
            unsigned xO = sbase + (unsigned)(kwin & 1) * XS_BYTES;
            unsigned bA0 = xO + (unsigned)(((wn * 2 + ky) * 18 + pxc + kx) * XS_STRIDE)
                           + bCol16;
            unsigned bA1 = bA0 + 18 * XS_STRIDE;

            #pragma unroll
            for (int kb = 0; kb < 4; kb++) {
                unsigned bq0, bq1, bq2, bq3, bq4, bq5, bq6, bq7;
                LDSM4(bq0, bq1, bq2, bq3, bA0 + kb * 32);
                LDSM4(bq4, bq5, bq6, bq7, bA1 + kb * 32);
                #pragma unroll
                for (int mi = 0; mi < 4; mi++) {
                    unsigned a0, a1, a2, a3;
                    LDSM4(a0, a1, a2, a3, aB + mi * (16 * XS_STRIDE) + kb * 32);
                    MMA16816(acc[mi][0], a0, a1, a2, a3, bq0, bq1);
                    MMA16816(acc[mi][1], a0, a1, a2, a3, bq2, bq3);
                    MMA16816(acc[mi][2], a0, a1, a2, a3, bq4, bq5);
                    MMA16816(acc[mi][3], a0, a1, a2, a3, bq6, bq7);
                }
            }
        }

        cp_wait1();
        __syncthreads();
    }

    // epilogue: D[co][pix] * demod + bias -> g_A
    #pragma unroll
    for (int mi = 0; mi < 4; mi++) {
        int coL = co0 + wm * 64 + mi * 16 + g;
        int coH = coL + 8;
        float ggL = g_g[(b << 9) + coL], bbL = act_b[coL];
        float ggH = g_g[(b << 9) + coH], bbH = act_b[coH];
        float* apL = g_A + (long)((b << 9) + coL) * (HC * HC);
        float* apH = g_A + (long)((b << 9) + coH) * (HC * HC);
        #pragma unroll
        for (int ni = 0; ni < 4; ni++) {
            int p0 = wn * 32 + ni * 8;
            int py = p0 >> 4, px = (p0 & 15) + 2 * t4;
            int oy = y0 + py, ox = x0 + px;
            if (oy < HC) {
                if (ox < HC) {
                    apL[oy * HC + ox] = acc[mi][ni][0] * ggL + bbL;
                    apH[oy * HC + ox] = acc[mi][ni][2] * ggH + bbH;
                }
                if (ox + 1 < HC) {
                    apL[oy * HC + ox + 1] = acc[mi][ni][1] * ggL + bbL;
                    apH[oy * HC + ox + 1] = acc[mi][ni][3] * ggH + bbH;
                }
            }
        }
    }
}

// ------------------------- L5: fused filter chain --------------------------
#define SMEM_FILT_BYTES (28440 * 4)

__global__ __launch_bounds__(256)
void k_filter(const float* __restrict__ uf, const float* __restrict__ df,
              float* __restrict__ out) {
    extern __shared__ float sm[];
    float* sA  = sm;
    float* sB  = sm + 3906;
    float* sC  = sm + 11904;
    float* sD  = sm;
    float* kfu = sm + 28416;
    float* kfd = sm + 28428;

    int p   = blockIdx.x;
    int tid = threadIdx.x;

    if (tid < NTAPS)          kfu[tid] = uf[tid] * 2.0f;
    else if (tid < 2 * NTAPS) kfd[tid - NTAPS] = df[tid - NTAPS];

    const float* Ap = g_A + (long)p * (HC * HC);
    for (int i = tid; i < HC * HC; i += 256) {
        int r = i / HC, c = i - r * HC;
        sA[r * 63 + c] = Ap[i];
    }
    __syncthreads();

    for (int i = tid; i < HC * HU; i += 256) {
        int n = i & 127, y = i >> 7;
        const float* row = sA + y * 63;
        float acc = 0.f;
        int s0 = (n + 3) & 1;
        #pragma unroll
        for (int q = 0; q < 6; q++) {
            int s = s0 + 2 * q;
            int j = (n + 3 - s) >> 1;
            if ((unsigned)j < (unsigned)HC) acc += kfu[s] * row[j];
        }
        sB[y * 129 + n] = acc;
    }
    __syncthreads();

    for (int i = tid; i < HU * HU; i += 256) {
        int xcol = i & 127, m = i >> 7;
        float acc = 0.f;
        int s0 = (m + 3) & 1;
        #pragma unroll
        for (int q = 0; q < 6; q++) {
            int s = s0 + 2 * q;
            int j = (m + 3 - s) >> 1;
            if ((unsigned)j < (unsigned)HC) acc += kfu[s] * sB[j * 129 + xcol];
        }
        acc = (acc >= 0.f ? acc : NEG_SLOPE * acc) * LRELU_SC;
        sC[m * 129 + xcol] = acc;
    }
    __syncthreads();

    for (int i = tid; i < HU * 64; i += 256) {
        int n = i & 63, y = i >> 6;
        const float* row = sC + y * 129;
        float acc = 0.f;
        #pragma unroll
        for (int s = 0; s < NTAPS; s++) {
            int j = 2 * n + 6 - s;
            if ((unsigned)j < (unsigned)HU) acc += kfd[s] * row[j];
        }
        sD[y * 65 + n] = acc;
    }
    __syncthreads();

    float* op = out + (long)p * (64 * 64);
    for (int i = tid; i < 64 * 64; i += 256) {
        int xcol = i & 63, m = i >> 6;
        float acc = 0.f;
        #pragma unroll
        for (int s = 0; s < NTAPS; s++) {
            int j = 2 * m + 6 - s;
            if ((unsigned)j < (unsigned)HU) acc += kfd[s] * sD[j * 65 + xcol];
        }
        op[i] = acc;
    }
}

// ---------------------------------------------------------------------------
extern "C" void kernel_launch(void* const* d_in, const int* in_sizes, int n_in,
                              void* d_out, int out_size) {
    const float* x      = (const float*)d_in[0];
    const float* style  = (const float*)d_in[1];
    const float* mod_w  = (const float*)d_in[2];
    const float* mod_b  = (const float*)d_in[3];
    const float* conv_w = (const float*)d_in[4];
    const float* act_b  = (const float*)d_in[5];
    const float* up_f   = (const float*)d_in[6];
    const float* down_f = (const float*)d_in[7];
    float* out = (float*)d_out;

    cudaFuncSetAttribute(k_filter, cudaFuncAttributeMaxDynamicSharedMemorySize,
                         SMEM_FILT_BYTES);
    cudaFuncSetAttribute(k_conv_mma, cudaFuncAttributeMaxDynamicSharedMemorySize,
                         SMEM_CONV2);

    k_pre1<<<1536 + 4096, 256>>>(style, mod_w, mod_b, conv_w);   // #1
    k_pre2<<<512 + 9216, 256>>>(conv_w);                          // #2
    k_prep_x<<<BATCH * 64 * 16 * 2, 256>>>(x);                    // #3
    k_conv_mma<<<BATCH * 4 * 8 * 4, 256, SMEM_CONV2>>>(act_b);    // #4 (profiled)
    k_filter<<<BATCH * COUT, 256, SMEM_FILT_BYTES>>>(up_f, down_f, out);  // #5
}

// round 11
// speedup vs baseline: 1.4210x; 1.4210x over previous
#include <cuda_runtime.h>
#include <cuda_fp16.h>
#include <math.h>

// ---------------------------------------------------------------------------
// AliasFreeConv: modulated 3x3 conv (demod) + 2x up (12-tap) + lrelu + 2x down
// Conv: fp16 2-pass (whi + wlo, x rounded once) implicit GEMM on mma.sync.
// R11: fp16 2-pass (144 iters), paired iterations (72 barriers), swizzled
// smem (4 W bufs + 2 X bufs, 2 CTAs/SM), wait_group 0 hidden under compute.
// Launch order: pre1, pre2, prep_x, conv(#4 - profiled), filter.
// ---------------------------------------------------------------------------

#define BATCH 8
#define CIN   512
#define COUT  512
#define HW    64
#define HC    62
#define HU    128
#define NTAPS 12
#define XP    68              // padded spatial for channels-last input

#define LIN_SCALE 0.044194173824159216f   // 1/sqrt(512)
#define WSCALE    0.014731391274719742f   // 1/sqrt(512*9)
#define WSCALE2   2.170138888888889e-4f   // 1/4608
#define EPSV      1e-8f
#define NEG_SLOPE 0.2f
#define LRELU_SC  1.4142135623730951f

#define XT_ELEMS (BATCH*XP*XP*512)        // 18,939,904 fp16
#define WT_ELEMS (9*512*512)              // 2,359,296 fp16

// ------------------------- scratch (device globals) ------------------------
__device__ float g_s  [BATCH*CIN];
__device__ float g_g  [BATCH*COUT];
__device__ float g_wsq[COUT*CIN];
__device__ float g_A  [BATCH*COUT*HC*HC];          // conv output (63 MB)
__device__ __align__(16) __half g_xh [XT_ELEMS];   // fp16(x*wscale*s)
__device__ __align__(16) __half g_whi[WT_ELEMS];   // [tap][co][ci] fp16 hi
__device__ __align__(16) __half g_wlo[WT_ELEMS];   // fp16 lo residual

// ------------------------- PTX helpers -------------------------------------
__device__ __forceinline__ unsigned smem_u32(const void* p) {
    unsigned a;
    asm("{ .reg .u64 t; cvta.to.shared.u64 t, %1; cvt.u32.u64 %0, t; }"
        : "=r"(a) : "l"(p));
    return a;
}
__device__ __forceinline__ void cp16(unsigned dst, const void* src) {
    asm volatile("cp.async.cg.shared.global [%0], [%1], 16;"
                 :: "r"(dst), "l"(src) : "memory");
}
__device__ __forceinline__ void cp_commit() {
    asm volatile("cp.async.commit_group;" ::: "memory");
}
__device__ __forceinline__ void cp_wait0() {
    asm volatile("cp.async.wait_group 0;" ::: "memory");
}
#define MMA16816(d, a0, a1, a2, a3, b0, b1) \
    asm volatile("mma.sync.aligned.m16n8k16.row.col.f32.f16.f16.f32 " \
        "{%0,%1,%2,%3}, {%4,%5,%6,%7}, {%8,%9}, {%0,%1,%2,%3};" \
        : "+f"((d)[0]), "+f"((d)[1]), "+f"((d)[2]), "+f"((d)[3]) \
        : "r"(a0), "r"(a1), "r"(a2), "r"(a3), "r"(b0), "r"(b1))
#define LDSM4(r0, r1, r2, r3, addr) \
    asm volatile("ldmatrix.sync.aligned.m8n8.x4.shared.b16 {%0,%1,%2,%3}, [%4];" \
        : "=r"(r0), "=r"(r1), "=r"(r2), "=r"(r3) : "r"(addr))

// ------------------------- L1: style + wsq + zero x_t ----------------------
__global__ __launch_bounds__(256)
void k_pre1(const float* __restrict__ style, const float* __restrict__ mod_w,
            const float* __restrict__ mod_b, const float* __restrict__ cw) {
    int bid = blockIdx.x;
    int tid = threadIdx.x;
    if (bid < 512) {
        int w    = bid * 8 + (tid >> 5);
        int lane = tid & 31;
        int b = w >> 9, c = w & 511;
        const float* sp = style + b * 512;
        const float* mp = mod_w + c * 512;
        float sum = 0.f;
        #pragma unroll 4
        for (int d = lane; d < 512; d += 32) sum += sp[d] * mp[d];
        #pragma unroll
        for (int off = 16; off; off >>= 1)
            sum += __shfl_xor_sync(0xffffffffu, sum, off);
        if (lane == 0) g_s[w] = sum * LIN_SCALE + mod_b[c];
    } else if (bid < 1536) {
        int i = (bid - 512) * 256 + tid;
        if (i < COUT * CIN) {
            float s = 0.f;
            #pragma unroll
            for (int k = 0; k < 9; k++) { float v = cw[i * 9 + k]; s += v * v; }
            g_wsq[i] = s;
        }
    } else {
        uint4 z = make_uint4(0u, 0u, 0u, 0u);
        uint4* a = reinterpret_cast<uint4*>(g_xh);
        int n = XT_ELEMS / 8;
        for (int i = (bid - 1536) * 256 + tid; i < n; i += 4096 * 256) a[i] = z;
    }
}

// ------------------------- L2: demod + prep_w ------------------------------
__global__ __launch_bounds__(256)
void k_pre2(const float* __restrict__ cw) {
    int bid = blockIdx.x;
    int tid = threadIdx.x;
    if (bid < 512) {
        int w    = bid * 8 + (tid >> 5);
        int lane = tid & 31;
        int b = w >> 9, co = w & 511;
        const float* sp = g_s   + b  * 512;
        const float* wq = g_wsq + co * 512;
        float sum = 0.f;
        #pragma unroll 4
        for (int d = lane; d < 512; d += 32) {
            float sv = sp[d]; sum += sv * sv * wq[d];
        }
        #pragma unroll
        for (int off = 16; off; off >>= 1)
            sum += __shfl_xor_sync(0xffffffffu, sum, off);
        if (lane == 0) g_g[w] = 1.0f / ((1.0f + EPSV) * sqrtf(WSCALE2 * sum + EPSV));
    } else {
        int i = (bid - 512) * 256 + tid;
        if (i < WT_ELEMS) {
            int ci  = i & 511;
            int co  = (i >> 9) & 511;
            int tap = i >> 18;
            float v = cw[(co * 512 + ci) * 9 + tap];
            __half hi = __float2half_rn(v);
            __half lo = __float2half_rn(v - __half2float(hi));
            g_whi[i] = hi;
            g_wlo[i] = lo;
        }
    }
}

// ------------------------- L3: x -> channels-last fp16 ---------------------
__global__ __launch_bounds__(256)
void k_prep_x(const float* __restrict__ x) {
    __shared__ float t[32][33];
    int bid  = blockIdx.x;                 // b(8) * y(64) * ciT(16) * xT(2)
    int xt   = bid & 1;
    int ci_t = (bid >> 1) & 15;
    int y    = (bid >> 5) & 63;
    int b    = bid >> 11;
    int tx = threadIdx.x & 31, ty = threadIdx.x >> 5;   // (32, 8)

    #pragma unroll
    for (int j = 0; j < 4; j++) {
        int ci = ci_t * 32 + ty + 8 * j;
        int xx = xt * 32 + tx;
        float v = x[((((b << 9) + ci) << 6) + y) * 64 + xx];
        t[ty + 8 * j][tx] = v * (WSCALE * g_s[(b << 9) + ci]);
    }
    __syncthreads();
    #pragma unroll
    for (int j = 0; j < 4; j++) {
        int xx = xt * 32 + ty + 8 * j;
        int ci = ci_t * 32 + tx;
        long o = ((long)(b * XP + y) * XP + xx) * 512 + ci;
        g_xh[o] = __float2half_rn(t[tx][ty + 8 * j]);
    }
}

// ------------------------- L4: mma.sync conv (fp16, paired) ----------------
// CTA tile: M=128 co x N=128 pixels (8y x 16x). 8 warps = 2(m) x 4(n),
// warp tile 64x32, mma m16n8k16 fp16. 144 K=64 iterations:
//   window k = i/18 (8 windows = ci chunks), t = i%18: whi taps 0..8 then
//   wlo taps 0..8, all against the same resident fp16 X chunk.
// Iterations run in pairs: [stage W(i+2),W(i+3) + X slices; commit; compute
// 2 taps; wait_group 0 (hidden under ~4096 cyc compute); barrier].
// Smem XOR-swizzled 128B rows (col16 ^= row&7): X 2x23040 @0, W 4x16384
// @46080 -> 111616 B total (2 CTAs/SM).
#define OFF_WS    46080u
#define WS_BYTES  16384u
#define XS_BYTES  23040u
#define SMEM_CONV 111616

__global__ __launch_bounds__(256, 2)
void k_conv_mma(const float* __restrict__ act_b) {
    extern __shared__ __align__(16) char smc[];
    unsigned sbase = smem_u32(smc);

    int tid  = threadIdx.x;
    int wid  = tid >> 5, lane = tid & 31;
    int g    = lane >> 2, t4 = lane & 3;
    int wm   = wid >> 2;                      // 0..1 -> co offset wm*64
    int wn   = wid & 3;                       // 0..3 -> pixel offset wn*32

    int bidx = blockIdx.x;                    // 1024 = b(8)*coT(4)*yT(8)*xT(4)
    int xT   = bidx & 3;
    int yT   = (bidx >> 2) & 7;
    int coT  = (bidx >> 5) & 3;
    int b    = bidx >> 7;
    int co0  = coT << 7;
    int y0   = yT << 3;
    int x0   = xT << 4;

    const __half* xB = g_xh + (long)b * XP * XP * 512;

    float acc[4][4][4];
    #pragma unroll
    for (int mi = 0; mi < 4; mi++)
        #pragma unroll
        for (int ni = 0; ni < 4; ni++)
            #pragma unroll
            for (int q = 0; q < 4; q++) acc[mi][ni][q] = 0.f;

    // ---- staging: W tile for iteration it -> buffer it&3 ----
    auto stageW = [&](int it) {
        int cch = it / 18, t = it - cch * 18;
        const __half* wb = (t < 9) ? g_whi : g_wlo;
        int tap = (t < 9) ? t : t - 9;
        const __half* wp = wb + ((long)tap << 18) + (long)co0 * 512 + (cch << 6);
        unsigned dst = sbase + OFF_WS + (unsigned)(it & 3) * WS_BYTES;
        #pragma unroll
        for (int k = 0; k < 4; k++) {                 // 1024 x 16B
            int c = tid + (k << 8);
            int row = c >> 3, cc = c & 7;
            cp16(dst + (unsigned)(row << 7) + (unsigned)(((cc ^ (row & 7)) << 4)),
                 wp + row * 512 + (cc << 3));
        }
    };
    // ---- staging: X window k (ci chunk k), segment seg (0..2, 480 ops) ----
    auto stageXseg = [&](int k, int seg) {
        const __half* xp = xB + (k << 6);
        unsigned dst = sbase + (unsigned)(k & 1) * XS_BYTES;
        int lo = seg * 480, hi = lo + 480;
        for (int c = lo + tid; c < hi; c += 256) {
            int row = c >> 3, cc = c & 7;
            int gy = y0 + row / 18, gx = x0 + row % 18;
            cp16(dst + (unsigned)(row << 7) + (unsigned)((cc ^ (row & 7)) << 4),
                 xp + (long)(gy * XP + gx) * 512 + (cc << 3));
        }
    };

    // per-lane fragment constants
    int r7  = lane & 7;                       // A row mod 8 (swizzle key)
    int cA  = lane >> 4;                      // A 16B-col base (0/1)
    unsigned rowByteA = (unsigned)((wm * 64 + (lane & 15)) << 7);
    int pxc = (((lane >> 4) & 1) << 3) + (lane & 7);
    int cB  = (lane >> 3) & 1;                // B 16B-col base (0/1)

    // ---- compute one K=64 iteration ----
    auto compute = [&](int i) {
        int kwin = i / 18, t = i - kwin * 18;
        int tap = (t < 9) ? t : t - 9;
        int ky = tap / 3, kx = tap - 3 * (tap / 3);
        unsigned wsB = sbase + OFF_WS + (unsigned)(i & 3) * WS_BYTES + rowByteA;
        unsigned xO  = sbase + (unsigned)(kwin & 1) * XS_BYTES;
        int rowB0 = (wn * 2 + ky) * 18 + pxc + kx;
        int rowB1 = rowB0 + 18;
        unsigned b0 = xO + (unsigned)(rowB0 << 7);
        unsigned b1 = xO + (unsigned)(rowB1 << 7);
        int s0 = rowB0 & 7, s1 = rowB1 & 7;

        #pragma unroll
        for (int kb = 0; kb < 4; kb++) {
            unsigned bq0, bq1, bq2, bq3, bq4, bq5, bq6, bq7;
            LDSM4(bq0, bq1, bq2, bq3, b0 + (unsigned)(((cB + 2 * kb) ^ s0) << 4));
            LDSM4(bq4, bq5, bq6, bq7, b1 + (unsigned)(((cB + 2 * kb) ^ s1) << 4));
            unsigned offA = (unsigned)(((cA + 2 * kb) ^ r7) << 4);
            #pragma unroll
            for (int mi = 0; mi < 4; mi++) {
                unsigned a0, a1, a2, a3;
                LDSM4(a0, a1, a2, a3, wsB + (unsigned)(mi * 2048) + offA);
                MMA16816(acc[mi][0], a0, a1, a2, a3, bq0, bq1);
                MMA16816(acc[mi][1], a0, a1, a2, a3, bq2, bq3);
                MMA16816(acc[mi][2], a0, a1, a2, a3, bq4, bq5);
                MMA16816(acc[mi][3], a0, a1, a2, a3, bq6, bq7);
            }
        }
    };

    // prologue: X window 0 (all 3 segments) + W(0), W(1)
    stageXseg(0, 0); stageXseg(0, 1); stageXseg(0, 2);
    stageW(0); stageW(1);
    cp_commit();
    cp_wait0();
    __syncthreads();

    // 72 pairs; windows (18 iters = 9 pairs) are pair-aligned
    #pragma unroll 1
    for (int p = 0; p < 72; p++) {
        int i0 = 2 * p;
        if (i0 + 2 < 144) stageW(i0 + 2);
        if (i0 + 3 < 144) stageW(i0 + 3);
        int kwin = p / 9, pp = p - kwin * 9;
        if (kwin < 7) {
            if (pp == 0) stageXseg(kwin + 1, 0);
            else if (pp == 1) { stageXseg(kwin + 1, 1); stageXseg(kwin + 1, 2); }
        }
        cp_commit();

        compute(i0);
        compute(i0 + 1);

        cp_wait0();          // copies issued this pair: complete under compute
        __syncthreads();
    }

    // epilogue: D[co][pix] * demod + bias -> g_A
    #pragma unroll
    for (int mi = 0; mi < 4; mi++) {
        int coL = co0 + wm * 64 + mi * 16 + g;
        int coH = coL + 8;
        float ggL = g_g[(b << 9) + coL], bbL = act_b[coL];
        float ggH = g_g[(b << 9) + coH], bbH = act_b[coH];
        float* apL = g_A + (long)((b << 9) + coL) * (HC * HC);
        float* apH = g_A + (long)((b << 9) + coH) * (HC * HC);
        #pragma unroll
        for (int ni = 0; ni < 4; ni++) {
            int p0 = wn * 32 + ni * 8;
            int py = p0 >> 4, px = (p0 & 15) + 2 * t4;
            int oy = y0 + py, ox = x0 + px;
            if (oy < HC) {
                if (ox < HC) {
                    apL[oy * HC + ox] = acc[mi][ni][0] * ggL + bbL;
                    apH[oy * HC + ox] = acc[mi][ni][2] * ggH + bbH;
                }
                if (ox + 1 < HC) {
                    apL[oy * HC + ox + 1] = acc[mi][ni][1] * ggL + bbL;
                    apH[oy * HC + ox + 1] = acc[mi][ni][3] * ggH + bbH;
                }
            }
        }
    }
}

// ------------------------- L5: fused filter chain --------------------------
#define SMEM_FILT_BYTES (28440 * 4)

__global__ __launch_bounds__(256)
void k_filter(const float* __restrict__ uf, const float* __restrict__ df,
              float* __restrict__ out) {
    extern __shared__ float sm[];
    float* sA  = sm;
    float* sB  = sm + 3906;
    float* sC  = sm + 11904;
    float* sD  = sm;
    float* kfu = sm + 28416;
    float* kfd = sm + 28428;

    int p   = blockIdx.x;
    int tid = threadIdx.x;

    if (tid < NTAPS)          kfu[tid] = uf[tid] * 2.0f;
    else if (tid < 2 * NTAPS) kfd[tid - NTAPS] = df[tid - NTAPS];

    const float* Ap = g_A + (long)p * (HC * HC);
    for (int i = tid; i < HC * HC; i += 256) {
        int r = i / HC, c = i - r * HC;
        sA[r * 63 + c] = Ap[i];
    }
    __syncthreads();

    for (int i = tid; i < HC * HU; i += 256) {
        int n = i & 127, y = i >> 7;
        const float* row = sA + y * 63;
        float acc = 0.f;
        int s0 = (n + 3) & 1;
        #pragma unroll
        for (int q = 0; q < 6; q++) {
            int s = s0 + 2 * q;
            int j = (n + 3 - s) >> 1;
            if ((unsigned)j < (unsigned)HC) acc += kfu[s] * row[j];
        }
        sB[y * 129 + n] = acc;
    }
    __syncthreads();

    for (int i = tid; i < HU * HU; i += 256) {
        int xcol = i & 127, m = i >> 7;
        float acc = 0.f;
        int s0 = (m + 3) & 1;
        #pragma unroll
        for (int q = 0; q < 6; q++) {
            int s = s0 + 2 * q;
            int j = (m + 3 - s) >> 1;
            if ((unsigned)j < (unsigned)HC) acc += kfu[s] * sB[j * 129 + xcol];
        }
        acc = (acc >= 0.f ? acc : NEG_SLOPE * acc) * LRELU_SC;
        sC[m * 129 + xcol] = acc;
    }
    __syncthreads();

    for (int i = tid; i < HU * 64; i += 256) {
        int n = i & 63, y = i >> 6;
        const float* row = sC + y * 129;
        float acc = 0.f;
        #pragma unroll
        for (int s = 0; s < NTAPS; s++) {
            int j = 2 * n + 6 - s;
            if ((unsigned)j < (unsigned)HU) acc += kfd[s] * row[j];
        }
        sD[y * 65 + n] = acc;
    }
    __syncthreads();

    float* op = out + (long)p * (64 * 64);
    for (int i = tid; i < 64 * 64; i += 256) {
        int xcol = i & 63, m = i >> 6;
        float acc = 0.f;
        #pragma unroll
        for (int s = 0; s < NTAPS; s++) {
            int j = 2 * m + 6 - s;
            if ((unsigned)j < (unsigned)HU) acc += kfd[s] * sD[j * 65 + xcol];
        }
        op[i] = acc;
    }
}

// ---------------------------------------------------------------------------
extern "C" void kernel_launch(void* const* d_in, const int* in_sizes, int n_in,
                              void* d_out, int out_size) {
    const float* x      = (const float*)d_in[0];
    const float* style  = (const float*)d_in[1];
    const float* mod_w  = (const float*)d_in[2];
    const float* mod_b  = (const float*)d_in[3];
    const float* conv_w = (const float*)d_in[4];
    const float* act_b  = (const float*)d_in[5];
    const float* up_f   = (const float*)d_in[6];
    const float* down_f = (const float*)d_in[7];
    float* out = (float*)d_out;

    cudaFuncSetAttribute(k_filter, cudaFuncAttributeMaxDynamicSharedMemorySize,
                         SMEM_FILT_BYTES);
    cudaFuncSetAttribute(k_conv_mma, cudaFuncAttributeMaxDynamicSharedMemorySize,
                         SMEM_CONV);

    k_pre1<<<1536 + 4096, 256>>>(style, mod_w, mod_b, conv_w);   // #1
    k_pre2<<<512 + 9216, 256>>>(conv_w);                          // #2
    k_prep_x<<<BATCH * 64 * 16 * 2, 256>>>(x);                    // #3
    k_conv_mma<<<BATCH * 4 * 8 * 4, 256, SMEM_CONV>>>(act_b);     // #4 (profiled)
    k_filter<<<BATCH * COUT, 256, SMEM_FILT_BYTES>>>(up_f, down_f, out);  // #5
}

// round 12
// speedup vs baseline: 2.0866x; 1.4684x over previous
#include <cuda_runtime.h>
#include <cuda_fp16.h>
#include <math.h>

// ---------------------------------------------------------------------------
// AliasFreeConv: modulated 3x3 conv (demod) + 2x up (12-tap) + lrelu + 2x down
// R12: single-pass fp16 implicit GEMM (72 K-iters) + half-plane filter blocks
// (66 KB smem -> 3 CTAs/SM). Launch: pre1, pre2, prep_x, conv(#4), filter.
// ---------------------------------------------------------------------------

#define BATCH 8
#define CIN   512
#define COUT  512
#define HW    64
#define HC    62
#define HU    128
#define NTAPS 12
#define XP    68              // padded spatial for channels-last input

#define LIN_SCALE 0.044194173824159216f   // 1/sqrt(512)
#define WSCALE    0.014731391274719742f   // 1/sqrt(512*9)
#define WSCALE2   2.170138888888889e-4f   // 1/4608
#define EPSV      1e-8f
#define NEG_SLOPE 0.2f
#define LRELU_SC  1.4142135623730951f

#define XT_ELEMS (BATCH*XP*XP*512)        // 18,939,904 fp16
#define WT_ELEMS (9*512*512)              // 2,359,296 fp16

// ------------------------- scratch (device globals) ------------------------
__device__ float g_s  [BATCH*CIN];
__device__ float g_g  [BATCH*COUT];
__device__ float g_wsq[COUT*CIN];
__device__ float g_A  [BATCH*COUT*HC*HC];          // conv output (63 MB)
__device__ __align__(16) __half g_xh [XT_ELEMS];   // fp16(x*wscale*s)
__device__ __align__(16) __half g_wh [WT_ELEMS];   // [tap][co][ci] fp16

// ------------------------- PTX helpers -------------------------------------
__device__ __forceinline__ unsigned smem_u32(const void* p) {
    unsigned a;
    asm("{ .reg .u64 t; cvta.to.shared.u64 t, %1; cvt.u32.u64 %0, t; }"
        : "=r"(a) : "l"(p));
    return a;
}
__device__ __forceinline__ void cp16(unsigned dst, const void* src) {
    asm volatile("cp.async.cg.shared.global [%0], [%1], 16;"
                 :: "r"(dst), "l"(src) : "memory");
}
__device__ __forceinline__ void cp_commit() {
    asm volatile("cp.async.commit_group;" ::: "memory");
}
__device__ __forceinline__ void cp_wait0() {
    asm volatile("cp.async.wait_group 0;" ::: "memory");
}
__device__ __forceinline__ void cp_wait1() {
    asm volatile("cp.async.wait_group 1;" ::: "memory");
}
#define MMA16816(d, a0, a1, a2, a3, b0, b1) \
    asm volatile("mma.sync.aligned.m16n8k16.row.col.f32.f16.f16.f32 " \
        "{%0,%1,%2,%3}, {%4,%5,%6,%7}, {%8,%9}, {%0,%1,%2,%3};" \
        : "+f"((d)[0]), "+f"((d)[1]), "+f"((d)[2]), "+f"((d)[3]) \
        : "r"(a0), "r"(a1), "r"(a2), "r"(a3), "r"(b0), "r"(b1))
#define LDSM4(r0, r1, r2, r3, addr) \
    asm volatile("ldmatrix.sync.aligned.m8n8.x4.shared.b16 {%0,%1,%2,%3}, [%4];" \
        : "=r"(r0), "=r"(r1), "=r"(r2), "=r"(r3) : "r"(addr))

// ------------------------- L1: style + wsq + zero x_t ----------------------
__global__ __launch_bounds__(256)
void k_pre1(const float* __restrict__ style, const float* __restrict__ mod_w,
            const float* __restrict__ mod_b, const float* __restrict__ cw) {
    int bid = blockIdx.x;
    int tid = threadIdx.x;
    if (bid < 512) {
        int w    = bid * 8 + (tid >> 5);
        int lane = tid & 31;
        int b = w >> 9, c = w & 511;
        const float* sp = style + b * 512;
        const float* mp = mod_w + c * 512;
        float sum = 0.f;
        #pragma unroll 4
        for (int d = lane; d < 512; d += 32) sum += sp[d] * mp[d];
        #pragma unroll
        for (int off = 16; off; off >>= 1)
            sum += __shfl_xor_sync(0xffffffffu, sum, off);
        if (lane == 0) g_s[w] = sum * LIN_SCALE + mod_b[c];
    } else if (bid < 1536) {
        int i = (bid - 512) * 256 + tid;
        if (i < COUT * CIN) {
            float s = 0.f;
            #pragma unroll
            for (int k = 0; k < 9; k++) { float v = cw[i * 9 + k]; s += v * v; }
            g_wsq[i] = s;
        }
    } else {
        uint4 z = make_uint4(0u, 0u, 0u, 0u);
        uint4* a = reinterpret_cast<uint4*>(g_xh);
        int n = XT_ELEMS / 8;
        for (int i = (bid - 1536) * 256 + tid; i < n; i += 4096 * 256) a[i] = z;
    }
}

// ------------------------- L2: demod + prep_w ------------------------------
__global__ __launch_bounds__(256)
void k_pre2(const float* __restrict__ cw) {
    int bid = blockIdx.x;
    int tid = threadIdx.x;
    if (bid < 512) {
        int w    = bid * 8 + (tid >> 5);
        int lane = tid & 31;
        int b = w >> 9, co = w & 511;
        const float* sp = g_s   + b  * 512;
        const float* wq = g_wsq + co * 512;
        float sum = 0.f;
        #pragma unroll 4
        for (int d = lane; d < 512; d += 32) {
            float sv = sp[d]; sum += sv * sv * wq[d];
        }
        #pragma unroll
        for (int off = 16; off; off >>= 1)
            sum += __shfl_xor_sync(0xffffffffu, sum, off);
        if (lane == 0) g_g[w] = 1.0f / ((1.0f + EPSV) * sqrtf(WSCALE2 * sum + EPSV));
    } else {
        int i = (bid - 512) * 256 + tid;
        if (i < WT_ELEMS) {
            int ci  = i & 511;
            int co  = (i >> 9) & 511;
            int tap = i >> 18;
            g_wh[i] = __float2half_rn(cw[(co * 512 + ci) * 9 + tap]);
        }
    }
}

// ------------------------- L3: x -> channels-last fp16 ---------------------
__global__ __launch_bounds__(256)
void k_prep_x(const float* __restrict__ x) {
    __shared__ float t[32][33];
    int bid  = blockIdx.x;                 // b(8) * y(64) * ciT(16) * xT(2)
    int xt   = bid & 1;
    int ci_t = (bid >> 1) & 15;
    int y    = (bid >> 5) & 63;
    int b    = bid >> 11;
    int tx = threadIdx.x & 31, ty = threadIdx.x >> 5;   // (32, 8)

    #pragma unroll
    for (int j = 0; j < 4; j++) {
        int ci = ci_t * 32 + ty + 8 * j;
        int xx = xt * 32 + tx;
        float v = x[((((b << 9) + ci) << 6) + y) * 64 + xx];
        t[ty + 8 * j][tx] = v * (WSCALE * g_s[(b << 9) + ci]);
    }
    __syncthreads();
    #pragma unroll
    for (int j = 0; j < 4; j++) {
        int xx = xt * 32 + ty + 8 * j;
        int ci = ci_t * 32 + tx;
        long o = ((long)(b * XP + y) * XP + xx) * 512 + ci;
        g_xh[o] = __float2half_rn(t[tx][ty + 8 * j]);
    }
}

// ------------------------- L4: mma.sync conv (fp16, 1 pass) ----------------
// CTA tile: M=128 co x N=128 pixels (8y x 16x). 8 warps = 2(m) x 4(n),
// warp tile 64x32, mma m16n8k16 fp16. 72 K=64 iterations: window k = i/9
// (ci chunk), tap = i%9. W 4-buffered (prefetch distance 2, wait_group 1);
// X double-buffered, staged in 8 slices of 180 cp16 across each window.
// Smem XOR-swizzled 128B rows: X 2x23040 @0, W 4x16384 @46080 -> 111616 B.
#define OFF_WS    46080u
#define WS_BYTES  16384u
#define XS_BYTES  23040u
#define SMEM_CONV 111616

__global__ __launch_bounds__(256, 2)
void k_conv_mma(const float* __restrict__ act_b) {
    extern __shared__ __align__(16) char smc[];
    unsigned sbase = smem_u32(smc);

    int tid  = threadIdx.x;
    int wid  = tid >> 5, lane = tid & 31;
    int g    = lane >> 2, t4 = lane & 3;
    int wm   = wid >> 2;                      // 0..1 -> co offset wm*64
    int wn   = wid & 3;                       // 0..3 -> pixel offset wn*32

    int bidx = blockIdx.x;                    // 1024 = b(8)*coT(4)*yT(8)*xT(4)
    int xT   = bidx & 3;
    int yT   = (bidx >> 2) & 7;
    int coT  = (bidx >> 5) & 3;
    int b    = bidx >> 7;
    int co0  = coT << 7;
    int y0   = yT << 3;
    int x0   = xT << 4;

    const __half* xB = g_xh + (long)b * XP * XP * 512;

    float acc[4][4][4];
    #pragma unroll
    for (int mi = 0; mi < 4; mi++)
        #pragma unroll
        for (int ni = 0; ni < 4; ni++)
            #pragma unroll
            for (int q = 0; q < 4; q++) acc[mi][ni][q] = 0.f;

    // ---- staging: W tile for iteration it -> buffer it&3 ----
    auto stageW = [&](int it) {
        int cch = it / 9, tap = it - cch * 9;
        const __half* wp = g_wh + ((long)tap << 18) + (long)co0 * 512 + (cch << 6);
        unsigned dst = sbase + OFF_WS + (unsigned)(it & 3) * WS_BYTES;
        #pragma unroll
        for (int k = 0; k < 4; k++) {                 // 1024 x 16B
            int c = tid + (k << 8);
            int row = c >> 3, cc = c & 7;
            cp16(dst + (unsigned)(row << 7) + (unsigned)(((cc ^ (row & 7)) << 4)),
                 wp + row * 512 + (cc << 3));
        }
    };
    // ---- staging: X window k (ci chunk k), slice s (0..7, 180 cp16) ----
    auto stageXslice = [&](int k, int s) {
        const __half* xp = xB + (k << 6);
        unsigned dst = sbase + (unsigned)(k & 1) * XS_BYTES;
        int c = s * 180 + tid;
        if (tid < 180) {
            int row = c >> 3, cc = c & 7;
            int gy = y0 + row / 18, gx = x0 + row % 18;
            cp16(dst + (unsigned)(row << 7) + (unsigned)((cc ^ (row & 7)) << 4),
                 xp + (long)(gy * XP + gx) * 512 + (cc << 3));
        }
    };
    auto stageXfull = [&](int k) {
        const __half* xp = xB + (k << 6);
        unsigned dst = sbase + (unsigned)(k & 1) * XS_BYTES;
        for (int c = tid; c < 1440; c += 256) {
            int row = c >> 3, cc = c & 7;
            int gy = y0 + row / 18, gx = x0 + row % 18;
            cp16(dst + (unsigned)(row << 7) + (unsigned)((cc ^ (row & 7)) << 4),
                 xp + (long)(gy * XP + gx) * 512 + (cc << 3));
        }
    };

    // per-lane fragment constants
    int r7  = lane & 7;                       // A row mod 8 (swizzle key)
    int cA  = lane >> 4;                      // A 16B-col base (0/1)
    unsigned rowByteA = (unsigned)((wm * 64 + (lane & 15)) << 7);
    int pxc = (((lane >> 4) & 1) << 3) + (lane & 7);
    int cB  = (lane >> 3) & 1;                // B 16B-col base (0/1)

    // ---- compute one K=64 iteration ----
    auto compute = [&](int i) {
        int kwin = i / 9, tap = i - kwin * 9;
        int ky = tap / 3, kx = tap - 3 * (tap / 3);
        unsigned wsB = sbase + OFF_WS + (unsigned)(i & 3) * WS_BYTES + rowByteA;
        unsigned xO  = sbase + (unsigned)(kwin & 1) * XS_BYTES;
        int rowB0 = (wn * 2 + ky) * 18 + pxc + kx;
        int rowB1 = rowB0 + 18;
        unsigned b0 = xO + (unsigned)(rowB0 << 7);
        unsigned b1 = xO + (unsigned)(rowB1 << 7);
        int s0 = rowB0 & 7, s1 = rowB1 & 7;

        #pragma unroll
        for (int kb = 0; kb < 4; kb++) {
            unsigned bq0, bq1, bq2, bq3, bq4, bq5, bq6, bq7;
            LDSM4(bq0, bq1, bq2, bq3, b0 + (unsigned)(((cB + 2 * kb) ^ s0) << 4));
            LDSM4(bq4, bq5, bq6, bq7, b1 + (unsigned)(((cB + 2 * kb) ^ s1) << 4));
            unsigned offA = (unsigned)(((cA + 2 * kb) ^ r7) << 4);
            #pragma unroll
            for (int mi = 0; mi < 4; mi++) {
                unsigned a0, a1, a2, a3;
                LDSM4(a0, a1, a2, a3, wsB + (unsigned)(mi * 2048) + offA);
                MMA16816(acc[mi][0], a0, a1, a2, a3, bq0, bq1);
                MMA16816(acc[mi][1], a0, a1, a2, a3, bq2, bq3);
                MMA16816(acc[mi][2], a0, a1, a2, a3, bq4, bq5);
                MMA16816(acc[mi][3], a0, a1, a2, a3, bq6, bq7);
            }
        }
    };

    // prologue: X window 0 + W(0), W(1)
    stageXfull(0);
    stageW(0); stageW(1);
    cp_commit();
    cp_wait0();
    __syncthreads();

    #pragma unroll 1
    for (int i = 0; i < 72; i++) {
        if (i + 2 < 72) stageW(i + 2);
        int kwin = i / 9, pos = i - kwin * 9;
        if (pos < 8 && kwin < 7) stageXslice(kwin + 1, pos);
        cp_commit();

        compute(i);

        cp_wait1();
        __syncthreads();
    }

    // epilogue: D[co][pix] * demod + bias -> g_A
    #pragma unroll
    for (int mi = 0; mi < 4; mi++) {
        int coL = co0 + wm * 64 + mi * 16 + g;
        int coH = coL + 8;
        float ggL = g_g[(b << 9) + coL], bbL = act_b[coL];
        float ggH = g_g[(b << 9) + coH], bbH = act_b[coH];
        float* apL = g_A + (long)((b << 9) + coL) * (HC * HC);
        float* apH = g_A + (long)((b << 9) + coH) * (HC * HC);
        #pragma unroll
        for (int ni = 0; ni < 4; ni++) {
            int p0 = wn * 32 + ni * 8;
            int py = p0 >> 4, px = (p0 & 15) + 2 * t4;
            int oy = y0 + py, ox = x0 + px;
            if (oy < HC) {
                if (ox < HC) {
                    apL[oy * HC + ox] = acc[mi][ni][0] * ggL + bbL;
                    apH[oy * HC + ox] = acc[mi][ni][2] * ggH + bbH;
                }
                if (ox + 1 < HC) {
                    apL[oy * HC + ox + 1] = acc[mi][ni][1] * ggL + bbL;
                    apH[oy * HC + ox + 1] = acc[mi][ni][3] * ggH + bbH;
                }
            }
        }
    }
}

// ------------------------- L5: fused filter chain (half planes) ------------
// 2 blocks per (b,co) plane: output rows [0,32) / [32,64). Each block stages
// only the input rows it needs (+halo):
//   half0: A rows [0,36),  C rows [0,69)     half1: A rows [25,62), C rows [59,128)
// smem floats: sA@0 (40*63), sB@2520 (40*129), sC@7680 (69*129),
//              sD@0 (69*65, reuses sA/sB), kfu@16581, kfd@16593. 66420 B.
#define SMEM_FILT2 66420

__global__ __launch_bounds__(256)
void k_filter(const float* __restrict__ uf, const float* __restrict__ df,
              float* __restrict__ out) {
    extern __shared__ float sm[];
    float* sA  = sm;
    float* sB  = sm + 2520;
    float* sC  = sm + 7680;
    float* sD  = sm;                 // reuse (sA/sB dead by phase 3)
    float* kfu = sm + 16581;
    float* kfd = sm + 16593;

    int bid  = blockIdx.x;
    int half = bid & 1;
    int p    = bid >> 1;
    int tid  = threadIdx.x;

    int r0 = half ? 25 : 0;          // first A row staged
    int NR = half ? 37 : 36;         // A rows staged
    int j0 = half ? 59 : 0;          // first C row produced
    const int NJ = 69;               // C rows produced
    int m0 = half << 5;              // first output row

    if (tid < NTAPS)          kfu[tid] = uf[tid] * 2.0f;
    else if (tid < 2 * NTAPS) kfd[tid - NTAPS] = df[tid - NTAPS];

    // phase 0: load A rows [r0, r0+NR)
    const float* Ap = g_A + (long)p * (HC * HC);
    for (int i = tid; i < NR * HC; i += 256) {
        int r = i / HC, c = i - r * HC;
        sA[r * 63 + c] = Ap[(r0 + r) * HC + c];
    }
    __syncthreads();

    // phase 1: upsample x -> sB[NR][128]
    for (int i = tid; i < NR * HU; i += 256) {
        int n = i & 127, lr = i >> 7;
        const float* row = sA + lr * 63;
        float acc = 0.f;
        int s0 = (n + 3) & 1;
        #pragma unroll
        for (int q = 0; q < 6; q++) {
            int s = s0 + 2 * q;
            int j = (n + 3 - s) >> 1;
            if ((unsigned)j < (unsigned)HC) acc += kfu[s] * row[j];
        }
        sB[lr * 129 + n] = acc;
    }
    __syncthreads();

    // phase 2: upsample y + lrelu -> sC rows [j0, j0+NJ)
    for (int i = tid; i < NJ * HU; i += 256) {
        int xcol = i & 127, lj = i >> 7;
        int m = j0 + lj;                       // global C row
        float acc = 0.f;
        int s0 = (m + 3) & 1;
        #pragma unroll
        for (int q = 0; q < 6; q++) {
            int s = s0 + 2 * q;
            int jr = (m + 3 - s) >> 1;
            if ((unsigned)jr < (unsigned)HC) acc += kfu[s] * sB[(jr - r0) * 129 + xcol];
        }
        acc = (acc >= 0.f ? acc : NEG_SLOPE * acc) * LRELU_SC;
        sC[lj * 129 + xcol] = acc;
    }
    __syncthreads();

    // phase 3: downsample x -> sD[NJ][64]
    for (int i = tid; i < NJ * 64; i += 256) {
        int n = i & 63, lj = i >> 6;
        const float* row = sC + lj * 129;
        float acc = 0.f;
        #pragma unroll
        for (int s = 0; s < NTAPS; s++) {
            int j = 2 * n + 6 - s;
            if ((unsigned)j < (unsigned)HU) acc += kfd[s] * row[j];
        }
        sD[lj * 65 + n] = acc;
    }
    __syncthreads();

    // phase 4: downsample y -> out rows [m0, m0+32)
    float* op = out + (long)p * (64 * 64);
    for (int i = tid; i < 32 * 64; i += 256) {
        int xcol = i & 63, lm = i >> 6;
        int m = m0 + lm;
        float acc = 0.f;
        #pragma unroll
        for (int s = 0; s < NTAPS; s++) {
            int j = 2 * m + 6 - s;
            if ((unsigned)j < (unsigned)HU) acc += kfd[s] * sD[(j - j0) * 65 + xcol];
        }
        op[m * 64 + xcol] = acc;
    }
}

// ---------------------------------------------------------------------------
extern "C" void kernel_launch(void* const* d_in, const int* in_sizes, int n_in,
                              void* d_out, int out_size) {
    const float* x      = (const float*)d_in[0];
    const float* style  = (const float*)d_in[1];
    const float* mod_w  = (const float*)d_in[2];
    const float* mod_b  = (const float*)d_in[3];
    const float* conv_w = (const float*)d_in[4];
    const float* act_b  = (const float*)d_in[5];
    const float* up_f   = (const float*)d_in[6];
    const float* down_f = (const float*)d_in[7];
    float* out = (float*)d_out;

    cudaFuncSetAttribute(k_filter, cudaFuncAttributeMaxDynamicSharedMemorySize,
                         SMEM_FILT2);
    cudaFuncSetAttribute(k_conv_mma, cudaFuncAttributeMaxDynamicSharedMemorySize,
                         SMEM_CONV);

    k_pre1<<<1536 + 4096, 256>>>(style, mod_w, mod_b, conv_w);   // #1
    k_pre2<<<512 + 9216, 256>>>(conv_w);                          // #2
    k_prep_x<<<BATCH * 64 * 16 * 2, 256>>>(x);                    // #3
    k_conv_mma<<<BATCH * 4 * 8 * 4, 256, SMEM_CONV>>>(act_b);     // #4 (profiled)
    k_filter<<<BATCH * COUT * 2, 256, SMEM_FILT2>>>(up_f, down_f, out);  // #5
}

// round 15
// speedup vs baseline: 2.5649x; 1.2292x over previous
#include <cuda_runtime.h>
#include <cuda_fp16.h>
#include <math.h>

// ---------------------------------------------------------------------------
// AliasFreeConv: modulated 3x3 conv (demod) + 2x up (12-tap) + lrelu + 2x down
// R15 == R14 resubmit (container-failure retry).
// Conv: fp16 single-pass implicit GEMM, paired iterations (36 barriers),
//       X-slice parity shift (no pair writes a buffer it also reads).
// Filter: half-plane blocks + register-window coarsening.
// Launch: pre1, pre2, prep_x, conv(#4 - profiled), filter.
// ---------------------------------------------------------------------------

#define BATCH 8
#define CIN   512
#define COUT  512
#define HW    64
#define HC    62
#define HU    128
#define NTAPS 12
#define XP    68              // padded spatial for channels-last input

#define LIN_SCALE 0.044194173824159216f   // 1/sqrt(512)
#define WSCALE    0.014731391274719742f   // 1/sqrt(512*9)
#define WSCALE2   2.170138888888889e-4f   // 1/4608
#define EPSV      1e-8f
#define NEG_SLOPE 0.2f
#define LRELU_SC  1.4142135623730951f

#define XT_ELEMS (BATCH*XP*XP*512)        // 18,939,904 fp16
#define WT_ELEMS (9*512*512)              // 2,359,296 fp16

// ------------------------- scratch (device globals) ------------------------
__device__ float g_s  [BATCH*CIN];
__device__ float g_g  [BATCH*COUT];
__device__ float g_wsq[COUT*CIN];
__device__ float g_A  [BATCH*COUT*HC*HC];          // conv output (63 MB)
__device__ __align__(16) __half g_xh [XT_ELEMS];   // fp16(x*wscale*s)
__device__ __align__(16) __half g_wh [WT_ELEMS];   // [tap][co][ci] fp16

// ------------------------- PTX helpers -------------------------------------
__device__ __forceinline__ unsigned smem_u32(const void* p) {
    unsigned a;
    asm("{ .reg .u64 t; cvta.to.shared.u64 t, %1; cvt.u32.u64 %0, t; }"
        : "=r"(a) : "l"(p));
    return a;
}
__device__ __forceinline__ void cp16(unsigned dst, const void* src) {
    asm volatile("cp.async.cg.shared.global [%0], [%1], 16;"
                 :: "r"(dst), "l"(src) : "memory");
}
__device__ __forceinline__ void cp_commit() {
    asm volatile("cp.async.commit_group;" ::: "memory");
}
__device__ __forceinline__ void cp_wait0() {
    asm volatile("cp.async.wait_group 0;" ::: "memory");
}
#define MMA16816(d, a0, a1, a2, a3, b0, b1) \
    asm volatile("mma.sync.aligned.m16n8k16.row.col.f32.f16.f16.f32 " \
        "{%0,%1,%2,%3}, {%4,%5,%6,%7}, {%8,%9}, {%0,%1,%2,%3};" \
        : "+f"((d)[0]), "+f"((d)[1]), "+f"((d)[2]), "+f"((d)[3]) \
        : "r"(a0), "r"(a1), "r"(a2), "r"(a3), "r"(b0), "r"(b1))
#define LDSM4(r0, r1, r2, r3, addr) \
    asm volatile("ldmatrix.sync.aligned.m8n8.x4.shared.b16 {%0,%1,%2,%3}, [%4];" \
        : "=r"(r0), "=r"(r1), "=r"(r2), "=r"(r3) : "r"(addr))

// ------------------------- L1: style + wsq + zero x_t ----------------------
__global__ __launch_bounds__(256)
void k_pre1(const float* __restrict__ style, const float* __restrict__ mod_w,
            const float* __restrict__ mod_b, const float* __restrict__ cw) {
    int bid = blockIdx.x;
    int tid = threadIdx.x;
    if (bid < 512) {
        int w    = bid * 8 + (tid >> 5);
        int lane = tid & 31;
        int b = w >> 9, c = w & 511;
        const float* sp = style + b * 512;
        const float* mp = mod_w + c * 512;
        float sum = 0.f;
        #pragma unroll 4
        for (int d = lane; d < 512; d += 32) sum += sp[d] * mp[d];
        #pragma unroll
        for (int off = 16; off; off >>= 1)
            sum += __shfl_xor_sync(0xffffffffu, sum, off);
        if (lane == 0) g_s[w] = sum * LIN_SCALE + mod_b[c];
    } else if (bid < 1536) {
        int i = (bid - 512) * 256 + tid;
        if (i < COUT * CIN) {
            float s = 0.f;
            #pragma unroll
            for (int k = 0; k < 9; k++) { float v = cw[i * 9 + k]; s += v * v; }
            g_wsq[i] = s;
        }
    } else {
        uint4 z = make_uint4(0u, 0u, 0u, 0u);
        uint4* a = reinterpret_cast<uint4*>(g_xh);
        int n = XT_ELEMS / 8;
        for (int i = (bid - 1536) * 256 + tid; i < n; i += 4096 * 256) a[i] = z;
    }
}

// ------------------------- L2: demod + prep_w ------------------------------
__global__ __launch_bounds__(256)
void k_pre2(const float* __restrict__ cw) {
    int bid = blockIdx.x;
    int tid = threadIdx.x;
    if (bid < 512) {
        int w    = bid * 8 + (tid >> 5);
        int lane = tid & 31;
        int b = w >> 9, co = w & 511;
        const float* sp = g_s   + b  * 512;
        const float* wq = g_wsq + co * 512;
        float sum = 0.f;
        #pragma unroll 4
        for (int d = lane; d < 512; d += 32) {
            float sv = sp[d]; sum += sv * sv * wq[d];
        }
        #pragma unroll
        for (int off = 16; off; off >>= 1)
            sum += __shfl_xor_sync(0xffffffffu, sum, off);
        if (lane == 0) g_g[w] = 1.0f / ((1.0f + EPSV) * sqrtf(WSCALE2 * sum + EPSV));
    } else {
        int i = (bid - 512) * 256 + tid;
        if (i < WT_ELEMS) {
            int ci  = i & 511;
            int co  = (i >> 9) & 511;
            int tap = i >> 18;
            g_wh[i] = __float2half_rn(cw[(co * 512 + ci) * 9 + tap]);
        }
    }
}

// ------------------------- L3: x -> channels-last fp16 ---------------------
__global__ __launch_bounds__(256)
void k_prep_x(const float* __restrict__ x) {
    __shared__ float t[32][33];
    int bid  = blockIdx.x;                 // b(8) * y(64) * ciT(16) * xT(2)
    int xt   = bid & 1;
    int ci_t = (bid >> 1) & 15;
    int y    = (bid >> 5) & 63;
    int b    = bid >> 11;
    int tx = threadIdx.x & 31, ty = threadIdx.x >> 5;   // (32, 8)

    #pragma unroll
    for (int j = 0; j < 4; j++) {
        int ci = ci_t * 32 + ty + 8 * j;
        int xx = xt * 32 + tx;
        float v = x[((((b << 9) + ci) << 6) + y) * 64 + xx];
        t[ty + 8 * j][tx] = v * (WSCALE * g_s[(b << 9) + ci]);
    }
    __syncthreads();
    #pragma unroll
    for (int j = 0; j < 4; j++) {
        int xx = xt * 32 + ty + 8 * j;
        int ci = ci_t * 32 + tx;
        long o = ((long)(b * XP + y) * XP + xx) * 512 + ci;
        g_xh[o] = __float2half_rn(t[tx][ty + 8 * j]);
    }
}

// ------------------------- L4: mma.sync conv (fp16, paired) ----------------
// CTA tile: M=128 co x N=128 pixels (8y x 16x). 8 warps = 2(m) x 4(n),
// warp tile 64x32, mma m16n8k16 fp16. 72 K=64 iterations in 36 pairs:
// [stage W(i0+2),W(i0+3) + X slices; commit; compute 2 taps; wait0; barrier].
// X window k+1 staged in 8 slices across window k; slice schedule shifted by
// (kwin & 1) so no pair writes a buffer another compute in that pair reads.
// Smem XOR-swizzled 128B rows: X 2x23040 @0, W 4x16384 @46080 -> 111616 B.
#define OFF_WS    46080u
#define WS_BYTES  16384u
#define XS_BYTES  23040u
#define SMEM_CONV 111616

__global__ __launch_bounds__(256, 2)
void k_conv_mma(const float* __restrict__ act_b) {
    extern __shared__ __align__(16) char smc[];
    unsigned sbase = smem_u32(smc);

    int tid  = threadIdx.x;
    int wid  = tid >> 5, lane = tid & 31;
    int g    = lane >> 2, t4 = lane & 3;
    int wm   = wid >> 2;                      // 0..1 -> co offset wm*64
    int wn   = wid & 3;                       // 0..3 -> pixel offset wn*32

    int bidx = blockIdx.x;                    // 1024 = b(8)*coT(4)*yT(8)*xT(4)
    int xT   = bidx & 3;
    int yT   = (bidx >> 2) & 7;
    int coT  = (bidx >> 5) & 3;
    int b    = bidx >> 7;
    int co0  = coT << 7;
    int y0   = yT << 3;
    int x0   = xT << 4;

    const __half* xB = g_xh + (long)b * XP * XP * 512;

    float acc[4][4][4];
    #pragma unroll
    for (int mi = 0; mi < 4; mi++)
        #pragma unroll
        for (int ni = 0; ni < 4; ni++)
            #pragma unroll
            for (int q = 0; q < 4; q++) acc[mi][ni][q] = 0.f;

    auto stageW = [&](int it) {
        int cch = it / 9, tap = it - cch * 9;
        const __half* wp = g_wh + ((long)tap << 18) + (long)co0 * 512 + (cch << 6);
        unsigned dst = sbase + OFF_WS + (unsigned)(it & 3) * WS_BYTES;
        #pragma unroll
        for (int k = 0; k < 4; k++) {                 // 1024 x 16B
            int c = tid + (k << 8);
            int row = c >> 3, cc = c & 7;
            cp16(dst + (unsigned)(row << 7) + (unsigned)(((cc ^ (row & 7)) << 4)),
                 wp + row * 512 + (cc << 3));
        }
    };
    auto stageXslice = [&](int k, int s) {
        const __half* xp = xB + (k << 6);
        unsigned dst = sbase + (unsigned)(k & 1) * XS_BYTES;
        int c = s * 180 + tid;
        if (tid < 180) {
            int row = c >> 3, cc = c & 7;
            int gy = y0 + row / 18, gx = x0 + row % 18;
            cp16(dst + (unsigned)(row << 7) + (unsigned)((cc ^ (row & 7)) << 4),
                 xp + (long)(gy * XP + gx) * 512 + (cc << 3));
        }
    };
    auto stageXfull = [&](int k) {
        const __half* xp = xB + (k << 6);
        unsigned dst = sbase + (unsigned)(k & 1) * XS_BYTES;
        for (int c = tid; c < 1440; c += 256) {
            int row = c >> 3, cc = c & 7;
            int gy = y0 + row / 18, gx = x0 + row % 18;
            cp16(dst + (unsigned)(row << 7) + (unsigned)((cc ^ (row & 7)) << 4),
                 xp + (long)(gy * XP + gx) * 512 + (cc << 3));
        }
    };

    // per-lane fragment constants
    int r7  = lane & 7;
    int cA  = lane >> 4;
    unsigned rowByteA = (unsigned)((wm * 64 + (lane & 15)) << 7);
    int pxc = (((lane >> 4) & 1) << 3) + (lane & 7);
    int cB  = (lane >> 3) & 1;

    auto compute = [&](int i) {
        int kwin = i / 9, tap = i - kwin * 9;
        int ky = tap / 3, kx = tap - 3 * (tap / 3);
        unsigned wsB = sbase + OFF_WS + (unsigned)(i & 3) * WS_BYTES + rowByteA;
        unsigned xO  = sbase + (unsigned)(kwin & 1) * XS_BYTES;
        int rowB0 = (wn * 2 + ky) * 18 + pxc + kx;
        int rowB1 = rowB0 + 18;
        unsigned b0 = xO + (unsigned)(rowB0 << 7);
        unsigned b1 = xO + (unsigned)(rowB1 << 7);
        int s0 = rowB0 & 7, s1 = rowB1 & 7;

        #pragma unroll
        for (int kb = 0; kb < 4; kb++) {
            unsigned bq0, bq1, bq2, bq3, bq4, bq5, bq6, bq7;
            LDSM4(bq0, bq1, bq2, bq3, b0 + (unsigned)(((cB + 2 * kb) ^ s0) << 4));
            LDSM4(bq4, bq5, bq6, bq7, b1 + (unsigned)(((cB + 2 * kb) ^ s1) << 4));
            unsigned offA = (unsigned)(((cA + 2 * kb) ^ r7) << 4);
            #pragma unroll
            for (int mi = 0; mi < 4; mi++) {
                unsigned a0, a1, a2, a3;
                LDSM4(a0, a1, a2, a3, wsB + (unsigned)(mi * 2048) + offA);
                MMA16816(acc[mi][0], a0, a1, a2, a3, bq0, bq1);
                MMA16816(acc[mi][1], a0, a1, a2, a3, bq2, bq3);
                MMA16816(acc[mi][2], a0, a1, a2, a3, bq4, bq5);
                MMA16816(acc[mi][3], a0, a1, a2, a3, bq6, bq7);
            }
        }
    };

    // prologue: X window 0 + W(0), W(1)
    stageXfull(0);
    stageW(0); stageW(1);
    cp_commit();
    cp_wait0();
    __syncthreads();

    #pragma unroll 1
    for (int pp = 0; pp < 36; pp++) {
        int i0 = pp << 1, i1 = i0 + 1;
        if (i0 + 2 < 72) stageW(i0 + 2);
        if (i1 + 2 < 72) stageW(i1 + 2);
        // X slices: window kwin+1, slice (pos - (kwin&1)) when in [0,8)
        #pragma unroll
        for (int u = 0; u < 2; u++) {
            int i  = i0 + u;
            int kw = i / 9, ps = i - kw * 9;
            int sl = ps - (kw & 1);
            if (kw < 7 && sl >= 0 && sl < 8) stageXslice(kw + 1, sl);
        }
        cp_commit();

        compute(i0);
        compute(i1);

        cp_wait0();
        __syncthreads();
    }

    // epilogue: D[co][pix] * demod + bias -> g_A
    #pragma unroll
    for (int mi = 0; mi < 4; mi++) {
        int coL = co0 + wm * 64 + mi * 16 + g;
        int coH = coL + 8;
        float ggL = g_g[(b << 9) + coL], bbL = act_b[coL];
        float ggH = g_g[(b << 9) + coH], bbH = act_b[coH];
        float* apL = g_A + (long)((b << 9) + coL) * (HC * HC);
        float* apH = g_A + (long)((b << 9) + coH) * (HC * HC);
        #pragma unroll
        for (int ni = 0; ni < 4; ni++) {
            int p0 = wn * 32 + ni * 8;
            int py = p0 >> 4, px = (p0 & 15) + 2 * t4;
            int oy = y0 + py, ox = x0 + px;
            if (oy < HC) {
                if (ox < HC) {
                    apL[oy * HC + ox] = acc[mi][ni][0] * ggL + bbL;
                    apH[oy * HC + ox] = acc[mi][ni][2] * ggH + bbH;
                }
                if (ox + 1 < HC) {
                    apL[oy * HC + ox + 1] = acc[mi][ni][1] * ggL + bbL;
                    apH[oy * HC + ox + 1] = acc[mi][ni][3] * ggH + bbH;
                }
            }
        }
    }
}

// ------------------------- L5: fused filter chain (coarsened) --------------
// 2 blocks per (b,co) plane: output rows [0,32) / [32,64).
//   half0: A rows [0,36),  C rows [0,69)   half1: A rows [25,62), C rows [58,128)
// All phases use per-thread register windows with compile-time tap maps:
//   up (x or y): 10 loads -> 8 outputs x 6 taps  (kk = (d+3-s)/2 + 4)
//   down-x: float2 rows (stride 130, pair 64 zero-filled): 8 LDS.64 -> 2 outs
//   down-y: 18 row loads -> 4 outputs
// smem floats: sA@0 (2520), sB@2520 (5160), sC@7680 (70*130=9100),
//              sD@0 (70*65=4550, reuses sA/sB), kfu@16780, kfd@16792 -> 67216B
#define SMEM_FILT3 (16804 * 4)

__global__ __launch_bounds__(256)
void k_filter(const float* __restrict__ uf, const float* __restrict__ df,
              float* __restrict__ out) {
    extern __shared__ float sm[];
    float* sA  = sm;
    float* sB  = sm + 2520;
    float* sC  = sm + 7680;
    float* sD  = sm;                 // reuse (sA/sB dead by phase 3)
    float* kfu = sm + 16780;
    float* kfd = sm + 16792;

    int bid  = blockIdx.x;
    int half = bid & 1;
    int p    = bid >> 1;
    int tid  = threadIdx.x;

    int r0 = half ? 25 : 0;          // first A row staged
    int NR = half ? 37 : 36;         // A rows staged
    int j0 = half ? 58 : 0;          // first C row produced (even)
    int NJ = half ? 70 : 69;         // C rows produced
    int m0 = half << 5;              // first output row

    if (tid < NTAPS)          kfu[tid] = uf[tid] * 2.0f;
    else if (tid < 2 * NTAPS) kfd[tid - NTAPS] = df[tid - NTAPS];

    // phase 0: load A rows [r0, r0+NR)
    const float* Ap = g_A + (long)p * (HC * HC);
    for (int i = tid; i < NR * HC; i += 256) {
        int r = i / HC, c = i - r * HC;
        sA[r * 63 + c] = Ap[(r0 + r) * HC + c];
    }
    __syncthreads();

    // phase 1: up-x -> sB[NR][128]. 8 outputs per task from 10 loads.
    for (int i = tid; i < NR * 16; i += 256) {
        int t = i & 15, lr = i >> 4;
        int n0 = t << 3;
        int base = (n0 >> 1) - 4;
        const float* row = sA + lr * 63;
        float r[10];
        #pragma unroll
        for (int kk = 0; kk < 10; kk++) {
            int j = base + kk;
            r[kk] = ((unsigned)j < 62u) ? row[j] : 0.f;
        }
        float* orow = sB + lr * 129 + n0;
        #pragma unroll
        for (int d = 0; d < 8; d++) {
            const int s0 = (d + 3) & 1;
            float acc = 0.f;
            #pragma unroll
            for (int q = 0; q < 6; q++) {
                const int s  = s0 + 2 * q;
                const int kk = ((d + 3 - s) >> 1) + 4;   // compile-time
                acc += kfu[s] * r[kk];
            }
            orow[d] = acc;
        }
    }
    __syncthreads();

    // phase 2: up-y + lrelu -> sC rows [j0, j0+NJ). j0 even => taps fold.
    for (int i = tid; i < 9 * 128; i += 256) {
        int xcol = i & 127, gidx = i >> 7;
        int mg = j0 + (gidx << 3);
        int base = (mg >> 1) - 4;             // global A-row idx base
        float r[10];
        #pragma unroll
        for (int kk = 0; kk < 10; kk++) {
            int lr = base + kk - r0;
            r[kk] = ((unsigned)lr < (unsigned)NR) ? sB[lr * 129 + xcol] : 0.f;
        }
        #pragma unroll
        for (int d = 0; d < 8; d++) {
            const int s0 = (d + 3) & 1;
            float acc = 0.f;
            #pragma unroll
            for (int q = 0; q < 6; q++) {
                const int s  = s0 + 2 * q;
                const int kk = ((d + 3 - s) >> 1) + 4;
                acc += kfu[s] * r[kk];
            }
            acc = (acc >= 0.f ? acc : NEG_SLOPE * acc) * LRELU_SC;
            int lj = (gidx << 3) + d;
            if (lj < NJ) sC[lj * 130 + xcol] = acc;
        }
    }
    // zero-fill float2 pair 64 (elements 128,129) of each sC row
    for (int i = tid; i < 70; i += 256) {
        sC[i * 130 + 128] = 0.f;
        sC[i * 130 + 129] = 0.f;
    }
    __syncthreads();

    // phase 3: down-x -> sD[NJ][64]. 2 outputs per task from 8 LDS.64.
    for (int i = tid; i < NJ * 32; i += 256) {
        int t = i & 31, lj = i >> 5;
        int n0 = t << 1;
        const float2* row2 = (const float2*)(sC + lj * 130);
        float2 r2[8];
        #pragma unroll
        for (int kk = 0; kk < 8; kk++) {
            int pi = n0 - 3 + kk;
            r2[kk] = ((unsigned)pi < 65u) ? row2[pi] : make_float2(0.f, 0.f);
        }
        float a0 = 0.f, a1 = 0.f;
        #pragma unroll
        for (int kk = 0; kk < 8; kk++) {
            const int sx0 = 12 - 2 * kk, sy0 = 11 - 2 * kk;   // out n0
            const int sx1 = 14 - 2 * kk, sy1 = 13 - 2 * kk;   // out n0+1
            if (sx0 >= 0 && sx0 <= 11) a0 += kfd[sx0] * r2[kk].x;
            if (sy0 >= 0 && sy0 <= 11) a0 += kfd[sy0] * r2[kk].y;
            if (sx1 >= 0 && sx1 <= 11) a1 += kfd[sx1] * r2[kk].x;
            if (sy1 >= 0 && sy1 <= 11) a1 += kfd[sy1] * r2[kk].y;
        }
        sD[lj * 65 + n0]     = a0;
        sD[lj * 65 + n0 + 1] = a1;
    }
    __syncthreads();

    // phase 4: down-y -> out rows [m0, m0+32). 4 outputs per task, 18 loads.
    float* op = out + (long)p * 4096;
    for (int i = tid; i < 512; i += 256) {
        int xcol = i & 63, u = i >> 6;
        int mg = m0 + (u << 2);
        float r[18];
        #pragma unroll
        for (int kk = 0; kk < 18; kk++) {
            int j  = 2 * mg - 5 + kk;
            int lr = j - j0;
            r[kk] = ((unsigned)j < 128u && (unsigned)lr < (unsigned)NJ)
                        ? sD[lr * 65 + xcol] : 0.f;
        }
        #pragma unroll
        for (int d = 0; d < 4; d++) {
            float acc = 0.f;
            #pragma unroll
            for (int kk = 0; kk < 18; kk++) {
                const int s = 2 * d + 11 - kk;
                if (s >= 0 && s <= 11) acc += kfd[s] * r[kk];
            }
            op[(mg + d) * 64 + xcol] = acc;
        }
    }
}

// ---------------------------------------------------------------------------
extern "C" void kernel_launch(void* const* d_in, const int* in_sizes, int n_in,
                              void* d_out, int out_size) {
    const float* x      = (const float*)d_in[0];
    const float* style  = (const float*)d_in[1];
    const float* mod_w  = (const float*)d_in[2];
    const float* mod_b  = (const float*)d_in[3];
    const float* conv_w = (const float*)d_in[4];
    const float* act_b  = (const float*)d_in[5];
    const float* up_f   = (const float*)d_in[6];
    const float* down_f = (const float*)d_in[7];
    float* out = (float*)d_out;

    cudaFuncSetAttribute(k_filter, cudaFuncAttributeMaxDynamicSharedMemorySize,
                         SMEM_FILT3);
    cudaFuncSetAttribute(k_conv_mma, cudaFuncAttributeMaxDynamicSharedMemorySize,
                         SMEM_CONV);

    k_pre1<<<1536 + 4096, 256>>>(style, mod_w, mod_b, conv_w);   // #1
    k_pre2<<<512 + 9216, 256>>>(conv_w);                          // #2
    k_prep_x<<<BATCH * 64 * 16 * 2, 256>>>(x);                    // #3
    k_conv_mma<<<BATCH * 4 * 8 * 4, 256, SMEM_CONV>>>(act_b);     // #4 (profiled)
    k_filter<<<BATCH * COUT * 2, 256, SMEM_FILT3>>>(up_f, down_f, out);  // #5
}